// round 8
// baseline (speedup 1.0000x reference)
#include <cuda_runtime.h>
#include <cuda_bf16.h>

#define NQ 11
#define NDIM 2048                 // 1 << NQ
#define NLAYERS 5
#define NBLK (NLAYERS + 1)        // 6 YZY blocks
#define NMAT (NBLK * NQ)          // 66 fused matrices
#define W_SIZE (3 * NMAT)         // 198

__device__ __forceinline__ float2 cmul(float2 a, float2 b) {
    return make_float2(a.x * b.x - a.y * b.y, a.x * b.y + a.y * b.x);
}
// acc += a * b (complex)
__device__ __forceinline__ float2 cfma2(float2 a, float2 b, float2 acc) {
    acc.x = fmaf(a.x, b.x, fmaf(-a.y, b.y, acc.x));
    acc.y = fmaf(a.x, b.y, fmaf( a.y, b.x, acc.y));
    return acc;
}

// ---------- Compile-time GF(2) CNOT-ring tracking ----------
struct Tabs {
    unsigned v[NLAYERS][NQ];   // pair-XOR vectors (G columns) per layer/qubit
    unsigned r[NLAYERS][NQ];   // parity masks (F rows) per layer/qubit
    unsigned g[NQ];            // final G columns (trace permutation)
    int plo[NLAYERS][5];       // per 2-qubit pass: low free-bit position
    int phi[NLAYERS][5];       // per 2-qubit pass: high free-bit position
    int b10[NLAYERS];          // single-qubit pass bit position
};
constexpr int cffs(unsigned x) { int i = 0; while (!((x >> i) & 1)) i++; return i; }
constexpr Tabs make_tabs() {
    Tabs T{};
    unsigned frow[NQ]{}, gcol[NQ]{};
    for (int i = 0; i < NQ; i++) { frow[i] = 1u << i; gcol[i] = 1u << i; }
    for (int L = 0; L < NLAYERS; L++) {
        for (int q = 0; q < NQ; q++) {
            const int bc = NQ - 1 - q;
            const int bt = NQ - 1 - ((q + 1) % NQ);
            frow[bt] ^= frow[bc];
            gcol[bc] ^= gcol[bt];
        }
        for (int q = 0; q < NQ; q++) {
            T.v[L][q] = gcol[NQ - 1 - q];
            T.r[L][q] = frow[NQ - 1 - q];
        }
        for (int gp = 0; gp < 5; gp++) {
            unsigned v1 = T.v[L][2 * gp], v2 = T.v[L][2 * gp + 1];
            int b1 = cffs(v1);
            unsigned w2 = ((v2 >> b1) & 1) ? (v2 ^ v1) : v2;
            int b2 = cffs(w2);
            T.plo[L][gp] = b1 < b2 ? b1 : b2;
            T.phi[L][gp] = b1 < b2 ? b2 : b1;
        }
        T.b10[L] = cffs(T.v[L][10]);
    }
    for (int i = 0; i < NQ; i++) T.g[i] = gcol[i];
    return T;
}
constexpr Tabs TB = make_tabs();            // host-side: folded into immediates in macros
__constant__ Tabs dTB = make_tabs();        // device-side mirror for runtime accesses

__device__ __forceinline__ int decode_dimA(const int* p, int B, int out_size) {
    int d = -1;
    if (p) {
        int v = p[0];
        if (v >= 1 && v <= NQ) d = v;
        else {
            float f = __int_as_float(v);
            if (f >= 0.5f && f <= 11.5f) d = (int)(f + 0.5f);
        }
    }
    if (d < 1 || d > NQ) {
        for (int t = 1; t <= NQ; t++) {
            long long nc = (long long)B << (2 * t);
            if (nc == (long long)out_size || 2 * nc == (long long)out_size) { d = t; break; }
        }
    }
    if (d < 1 || d > NQ) d = 5;
    return d;
}

// ---------- per-pass macros: all masks are compile-time immediates ----------
#define PASS2(L, G) do {                                                         \
    constexpr unsigned v1 = TB.v[L][2*(G)], v2 = TB.v[L][2*(G)+1];               \
    constexpr unsigned r1 = TB.r[L][2*(G)], r2 = TB.r[L][2*(G)+1];               \
    constexpr int lo = TB.plo[L][G], hi = TB.phi[L][G];                          \
    const float2* Mp1 = fm[((L)+1)*NQ + 2*(G)];                                  \
    const float2* Mp2 = fm[((L)+1)*NQ + 2*(G)+1];                                \
    float2 m10 = Mp1[0], m11 = Mp1[1], m12 = Mp1[2], m13 = Mp1[3];               \
    float2 m20 = Mp2[0], m21 = Mp2[1], m22 = Mp2[2], m23 = Mp2[3];               \
    int p = ((tid >> lo) << (lo + 1)) | (tid & ((1 << lo) - 1));                 \
    p = ((p >> hi) << (hi + 1)) | (p & ((1 << hi) - 1));                         \
    int t1 = __popc((unsigned)p & r1) & 1;                                       \
    int t2 = __popc((unsigned)p & r2) & 1;                                       \
    p ^= (t1 ? (int)v1 : 0) ^ (t2 ? (int)v2 : 0);                                \
    int a1 = p ^ (int)v1, a2 = p ^ (int)v2, a3 = a1 ^ (int)v2;                   \
    float2 z0 = st[p], z1 = st[a1], z2 = st[a2], z3 = st[a3];                    \
    float2 n0 = cfma2(m11, z1, cmul(m10, z0));                                   \
    float2 n1 = cfma2(m13, z1, cmul(m12, z0));                                   \
    float2 n2 = cfma2(m11, z3, cmul(m10, z2));                                   \
    float2 n3 = cfma2(m13, z3, cmul(m12, z2));                                   \
    z0 = cfma2(m21, n2, cmul(m20, n0));                                          \
    z2 = cfma2(m23, n2, cmul(m22, n0));                                          \
    z1 = cfma2(m21, n3, cmul(m20, n1));                                          \
    z3 = cfma2(m23, n3, cmul(m22, n1));                                          \
    st[p] = z0; st[a1] = z1; st[a2] = z2; st[a3] = z3;                           \
    __syncthreads();                                                             \
} while (0)

#define PASS1(L) do {                                                            \
    constexpr unsigned v = TB.v[L][10], r = TB.r[L][10];                         \
    constexpr int b1 = TB.b10[L];                                                \
    const float2* Mp = fm[((L)+1)*NQ + 10];                                      \
    float2 m0 = Mp[0], m1 = Mp[1], m2 = Mp[2], m3 = Mp[3];                       \
    int pA = ((tid >> b1) << (b1 + 1)) | (tid & ((1 << b1) - 1));                \
    int ct = tid + 512;                                                          \
    int pB = ((ct >> b1) << (b1 + 1)) | (ct & ((1 << b1) - 1));                  \
    int tA = __popc((unsigned)pA & r) & 1;                                       \
    int tB = __popc((unsigned)pB & r) & 1;                                       \
    pA ^= tA ? (int)v : 0;  pB ^= tB ? (int)v : 0;                               \
    int pA1 = pA ^ (int)v, pB1 = pB ^ (int)v;                                    \
    float2 zA0 = st[pA], zA1 = st[pA1], zB0 = st[pB], zB1 = st[pB1];             \
    st[pA]  = cfma2(m1, zA1, cmul(m0, zA0));                                     \
    st[pA1] = cfma2(m3, zA1, cmul(m2, zA0));                                     \
    st[pB]  = cfma2(m1, zB1, cmul(m0, zB0));                                     \
    st[pB1] = cfma2(m3, zB1, cmul(m2, zB0));                                     \
    __syncthreads();                                                             \
} while (0)

#define LAYER(L) do { PASS2(L,0); PASS2(L,1); PASS2(L,2); PASS2(L,3); PASS2(L,4); PASS1(L); } while (0)

__global__ __launch_bounds__(512, 1)
void qsim_kernel(const float* __restrict__ x,
                 const float* __restrict__ w,
                 const int* __restrict__ dimA_p,
                 void* __restrict__ out_v,
                 int B, int out_size)
{
    __shared__ float2 st[NDIM];                 // statevector (16 KB)
    __shared__ float2 fm[NMAT][4];              // fused YZY matrices
    __shared__ float2 u[NQ][2];                 // embed*YZY0 column coefs
    __shared__ int physA[32], physB[64];        // trace index tables
    __shared__ float partial[4][1024];          // trace partials (16 KB)

    const int tid = threadIdx.x;
    const int b   = blockIdx.x;

    // ---- Fused M = Ry(t2) Rz(t1) Ry(t0) ----
    if (tid < NMAT) {
        int base = tid * 3;
        float t0 = w[base], t1 = w[base + 1], t2 = w[base + 2];
        float c0, s0, c1, s1, c2, s2;
        sincosf(0.5f * t0, &s0, &c0);
        sincosf(0.5f * t1, &s1, &c1);
        sincosf(0.5f * t2, &s2, &c2);
        float2 em = make_float2(c1, -s1);
        float2 ep = make_float2(c1,  s1);
        fm[tid][0] = make_float2( c2*c0*em.x - s2*s0*ep.x,  c2*c0*em.y - s2*s0*ep.y);
        fm[tid][1] = make_float2(-c2*s0*em.x - s2*c0*ep.x, -c2*s0*em.y - s2*c0*ep.y);
        fm[tid][2] = make_float2( s2*c0*em.x + c2*s0*ep.x,  s2*c0*em.y + c2*s0*ep.y);
        fm[tid][3] = make_float2(-s2*s0*em.x + c2*c0*ep.x, -s2*s0*em.y + c2*c0*ep.y);
    }
    // ---- Embedding fused into block 0 ----
    if (tid < NQ) {
        float sh, ch;
        sincosf(0.5f * x[b * NQ + tid], &sh, &ch);
        const float2* M = fm[tid];
        u[tid][0] = make_float2(M[0].x*ch + M[1].x*sh, M[0].y*ch + M[1].y*sh);
        u[tid][1] = make_float2(M[2].x*ch + M[3].x*sh, M[2].y*ch + M[3].y*sh);
    }
    // ---- Trace permutation tables (runtime device reads via dTB) ----
    if (tid >= 64 && tid < 96) {
        int j = tid - 64; unsigned ph = 0;
        #pragma unroll
        for (int bit = 0; bit < 5; bit++) if ((j >> bit) & 1) ph ^= dTB.g[bit];
        physA[j] = (int)ph;
    }
    if (tid < 64) {
        int i = tid; unsigned ph = 0;
        #pragma unroll
        for (int bit = 0; bit < 6; bit++) if ((i >> bit) & 1) ph ^= dTB.g[5 + bit];
        physB[i] = (int)ph;
    }
    __syncthreads();

    // ---- Product-state init: 4 consecutive amps per thread ----
    {
        float2 hi = cmul(u[0][(tid >> 8) & 1], u[1][(tid >> 7) & 1]);
        hi = cmul(hi, u[2][(tid >> 6) & 1]);
        hi = cmul(hi, u[3][(tid >> 5) & 1]);
        hi = cmul(hi, u[4][(tid >> 4) & 1]);
        hi = cmul(hi, u[5][(tid >> 3) & 1]);
        hi = cmul(hi, u[6][(tid >> 2) & 1]);
        hi = cmul(hi, u[7][(tid >> 1) & 1]);
        hi = cmul(hi, u[8][tid & 1]);
        #pragma unroll
        for (int k = 0; k < 4; k++) {
            float2 lo = cmul(u[9][(k >> 1) & 1], u[10][k & 1]);
            st[(tid << 2) | k] = cmul(hi, lo);
        }
    }
    __syncthreads();

    // ---- Blocks 1..5: fully unrolled, all constants immediate ----
    LAYER(0); LAYER(1); LAYER(2); LAYER(3); LAYER(4);

    // ---- Partial trace: Re(rho[j,k]) = sum_i Re(psi_ij psi_ik*) ----
    const int dimA = decode_dimA(dimA_p, B, out_size);
    const int dA   = 1 << dimA;
    const int dB   = NDIM >> dimA;
    const int nOut = dA * dA;
    const bool real_only = ((long long)B * nOut == (long long)out_size);

    if (dimA == 5 && real_only) {
        // 4 i-groups x 128 threads; each thread computes a 2x4 tile over 16 i's
        int g  = tid >> 7;           // 0..3
        int ss = tid & 127;
        int j0 = (ss >> 3) * 2;      // rows: 16 pairs
        int k0 = (ss & 7) * 4;       // cols: 8 quads
        int paj0 = physA[j0], paj1 = physA[j0 + 1];
        int pak[4];
        #pragma unroll
        for (int d = 0; d < 4; d++) pak[d] = physA[k0 + d];
        float acc[2][4];
        #pragma unroll
        for (int a = 0; a < 2; a++)
            #pragma unroll
            for (int c = 0; c < 4; c++) acc[a][c] = 0.f;
        #pragma unroll
        for (int ii = 0; ii < 16; ii++) {
            int pb = physB[g * 16 + ii];
            float2 aj0 = st[pb ^ paj0];
            float2 aj1 = st[pb ^ paj1];
            #pragma unroll
            for (int c = 0; c < 4; c++) {
                float2 ak = st[pb ^ pak[c]];
                acc[0][c] = fmaf(aj0.x, ak.x, fmaf(aj0.y, ak.y, acc[0][c]));
                acc[1][c] = fmaf(aj1.x, ak.x, fmaf(aj1.y, ak.y, acc[1][c]));
            }
        }
        #pragma unroll
        for (int a = 0; a < 2; a++)
            #pragma unroll
            for (int c = 0; c < 4; c++)
                partial[g][(j0 + a) * 32 + (k0 + c)] = acc[a][c];
        __syncthreads();
        #pragma unroll
        for (int m = 0; m < 2; m++) {
            int o = tid * 2 + m;
            ((float*)out_v)[b * 1024 + o] =
                partial[0][o] + partial[1][o] + partial[2][o] + partial[3][o];
        }
    } else {
        // Generic fallback
        for (int o = tid; o < nOut; o += blockDim.x) {
            int j = o / dA;
            int k = o - j * dA;
            float2 acc = make_float2(0.f, 0.f);
            for (int i = 0; i < dB; i++) {
                int lj = i * dA + j, lk = i * dA + k;
                unsigned pj = 0, pk = 0;
                #pragma unroll
                for (int bit = 0; bit < NQ; bit++) {
                    if ((lj >> bit) & 1) pj ^= dTB.g[bit];
                    if ((lk >> bit) & 1) pk ^= dTB.g[bit];
                }
                float2 a = st[pj], c = st[pk];
                acc.x = fmaf(a.x, c.x, fmaf(a.y, c.y, acc.x));
                acc.y = fmaf(a.y, c.x, fmaf(-a.x, c.y, acc.y));
            }
            if (real_only) ((float*)out_v)[b * nOut + o] = acc.x;
            else           ((float2*)out_v)[b * nOut + o] = acc;
        }
    }
}

extern "C" void kernel_launch(void* const* d_in, const int* in_sizes, int n_in,
                              void* d_out, int out_size) {
    // Bind by element count (unique sizes): w=198, dimA=1, x = B*11
    const float* x = nullptr;
    const float* w = nullptr;
    const int* dimA_p = nullptr;
    int x_size = 0;
    for (int i = 0; i < n_in; i++) {
        if (in_sizes[i] == W_SIZE) w = (const float*)d_in[i];
        else if (in_sizes[i] == 1) dimA_p = (const int*)d_in[i];
        else { x = (const float*)d_in[i]; x_size = in_sizes[i]; }
    }
    if (!x) { x = (const float*)d_in[0]; x_size = in_sizes[0]; }
    if (!w) { w = (const float*)d_in[1]; }

    int B = x_size / NQ;   // 16
    qsim_kernel<<<B, 512>>>(x, w, dimA_p, d_out, B, out_size);
}

// round 9
// speedup vs baseline: 1.3222x; 1.3222x over previous
#include <cuda_runtime.h>
#include <cuda_bf16.h>

#define NQ 11
#define NDIM 2048                 // 1 << NQ
#define NLAYERS 5
#define NBLK (NLAYERS + 1)        // 6 YZY blocks
#define NMAT (NBLK * NQ)          // 66 fused matrices
#define W_SIZE (3 * NMAT)         // 198

__device__ __forceinline__ float2 cmul(float2 a, float2 b) {
    return make_float2(a.x * b.x - a.y * b.y, a.x * b.y + a.y * b.x);
}
// acc += a * b (complex)
__device__ __forceinline__ float2 cfma2(float2 a, float2 b, float2 acc) {
    acc.x = fmaf(a.x, b.x, fmaf(-a.y, b.y, acc.x));
    acc.y = fmaf(a.x, b.y, fmaf( a.y, b.x, acc.y));
    return acc;
}

// ---------- Compile-time GF(2) CNOT-ring tracking ----------
struct Tabs {
    unsigned v[NLAYERS][NQ];   // gate-axis XOR vectors (G columns) per layer/qubit
    unsigned g[NQ];            // final G columns (trace permutation)
};
constexpr Tabs make_tabs() {
    Tabs T{};
    unsigned frow[NQ]{}, gcol[NQ]{};
    for (int i = 0; i < NQ; i++) { frow[i] = 1u << i; gcol[i] = 1u << i; }
    for (int L = 0; L < NLAYERS; L++) {
        for (int q = 0; q < NQ; q++) {
            const int bc = NQ - 1 - q;
            const int bt = NQ - 1 - ((q + 1) % NQ);
            frow[bt] ^= frow[bc];
            gcol[bc] ^= gcol[bt];
        }
        for (int q = 0; q < NQ; q++) T.v[L][q] = gcol[NQ - 1 - q];
    }
    for (int i = 0; i < NQ; i++) T.g[i] = gcol[i];
    return T;
}
constexpr Tabs TB = make_tabs();            // compile-time folded constants
__constant__ Tabs dTB = make_tabs();        // device mirror for runtime accesses

__device__ __forceinline__ int decode_dimA(const int* p, int B, int out_size) {
    int d = -1;
    if (p) {
        int v = p[0];
        if (v >= 1 && v <= NQ) d = v;
        else {
            float f = __int_as_float(v);
            if (f >= 0.5f && f <= 11.5f) d = (int)(f + 0.5f);
        }
    }
    if (d < 1 || d > NQ) {
        for (int t = 1; t <= NQ; t++) {
            long long nc = (long long)B << (2 * t);
            if (nc == (long long)out_size || 2 * nc == (long long)out_size) { d = t; break; }
        }
    }
    if (d < 1 || d > NQ) d = 5;
    return d;
}

// SU(2) gate M = [[a, -conj(b)], [b, conj(a)]] on a register pair (za, zb).
__device__ __forceinline__ void reg_gate(float2& za, float2& zb, float2 al, float2 be) {
    float2 nbc = make_float2(-be.x,  be.y);   // -conj(beta)
    float2 cal = make_float2( al.x, -al.y);   //  conj(alpha)
    float2 t = cfma2(nbc, zb, cmul(al, za));
    zb = cfma2(cal, zb, cmul(be, za));
    za = t;
}

// SU(2) gate along a lane bit: partner amps come via shfl.xor.
template<int MASK>
__device__ __forceinline__ void lane_gate(float2 z[4], float2 al, float2 be, int lane) {
    bool bit = (lane & MASK) != 0;
    float2 ca = make_float2(al.x, bit ? -al.y : al.y);            // alpha or conj(alpha)
    float2 cb = bit ? be : make_float2(-be.x, be.y);              // beta or -conj(beta)
    #pragma unroll
    for (int k = 0; k < 4; k++) {
        float2 zp;
        zp.x = __shfl_xor_sync(0xffffffffu, z[k].x, MASK);
        zp.y = __shfl_xor_sync(0xffffffffu, z[k].y, MASK);
        z[k] = cfma2(cb, zp, cmul(ca, z[k]));
    }
}

// One YZY block (block L+1) entirely in y-coordinates: p(y) = XOR of v_q for set y_q.
// Round 1: y0,y1 = register bits, y2..y6 = lane bits (gates q0..q6).
// Round 2: y7,y8 = register bits, y9,y10 = lane bits  (gates q7..q10).
template<int L>
__device__ __forceinline__ void do_layer(float2* st, const float2* Am, const float2* Bm, int tid) {
    constexpr unsigned v0 = TB.v[L][0],  v1 = TB.v[L][1],  v2 = TB.v[L][2];
    constexpr unsigned v3 = TB.v[L][3],  v4 = TB.v[L][4],  v5 = TB.v[L][5];
    constexpr unsigned v6 = TB.v[L][6],  v7 = TB.v[L][7],  v8 = TB.v[L][8];
    constexpr unsigned v9 = TB.v[L][9],  v10 = TB.v[L][10];
    const int lane = tid & 31, wrp = tid >> 5;
    const int mb = (L + 1) * NQ;
    float2 z[4];

    // ---- Round 1 ----
    {
        unsigned base = ((lane & 1) ? v2 : 0u) ^ ((lane & 2) ? v3 : 0u)
                      ^ ((lane & 4) ? v4 : 0u) ^ ((lane & 8) ? v5 : 0u)
                      ^ ((lane & 16) ? v6 : 0u)
                      ^ ((wrp & 1) ? v7 : 0u) ^ ((wrp & 2) ? v8 : 0u)
                      ^ ((wrp & 4) ? v9 : 0u) ^ ((wrp & 8) ? v10 : 0u);
        unsigned a0 = base, a1 = base ^ v0, a2 = base ^ v1, a3 = base ^ v0 ^ v1;
        z[0] = st[a0]; z[1] = st[a1]; z[2] = st[a2]; z[3] = st[a3];
        { float2 al = Am[mb + 0], be = Bm[mb + 0];
          reg_gate(z[0], z[1], al, be); reg_gate(z[2], z[3], al, be); }
        { float2 al = Am[mb + 1], be = Bm[mb + 1];
          reg_gate(z[0], z[2], al, be); reg_gate(z[1], z[3], al, be); }
        lane_gate<1 >(z, Am[mb + 2], Bm[mb + 2], lane);
        lane_gate<2 >(z, Am[mb + 3], Bm[mb + 3], lane);
        lane_gate<4 >(z, Am[mb + 4], Bm[mb + 4], lane);
        lane_gate<8 >(z, Am[mb + 5], Bm[mb + 5], lane);
        lane_gate<16>(z, Am[mb + 6], Bm[mb + 6], lane);
        st[a0] = z[0]; st[a1] = z[1]; st[a2] = z[2]; st[a3] = z[3];
        __syncthreads();
    }
    // ---- Round 2 ----
    {
        unsigned base = ((lane & 1) ? v9 : 0u) ^ ((lane & 2) ? v10 : 0u)
                      ^ ((lane & 4) ? v0 : 0u) ^ ((lane & 8) ? v1 : 0u)
                      ^ ((lane & 16) ? v2 : 0u)
                      ^ ((wrp & 1) ? v3 : 0u) ^ ((wrp & 2) ? v4 : 0u)
                      ^ ((wrp & 4) ? v5 : 0u) ^ ((wrp & 8) ? v6 : 0u);
        unsigned a0 = base, a1 = base ^ v7, a2 = base ^ v8, a3 = base ^ v7 ^ v8;
        z[0] = st[a0]; z[1] = st[a1]; z[2] = st[a2]; z[3] = st[a3];
        { float2 al = Am[mb + 7], be = Bm[mb + 7];
          reg_gate(z[0], z[1], al, be); reg_gate(z[2], z[3], al, be); }
        { float2 al = Am[mb + 8], be = Bm[mb + 8];
          reg_gate(z[0], z[2], al, be); reg_gate(z[1], z[3], al, be); }
        lane_gate<1>(z, Am[mb + 9],  Bm[mb + 9],  lane);
        lane_gate<2>(z, Am[mb + 10], Bm[mb + 10], lane);
        st[a0] = z[0]; st[a1] = z[1]; st[a2] = z[2]; st[a3] = z[3];
        __syncthreads();
    }
}

__global__ __launch_bounds__(512, 1)
void qsim_kernel(const float* __restrict__ x,
                 const float* __restrict__ w,
                 const int* __restrict__ dimA_p,
                 void* __restrict__ out_v,
                 int B, int out_size)
{
    __shared__ float2 st[NDIM];                 // statevector (16 KB)
    __shared__ float2 Am[NMAT];                 // alpha of each fused SU(2) matrix
    __shared__ float2 Bm[NMAT];                 // beta  of each fused SU(2) matrix
    __shared__ float2 u[NQ][2];                 // embed*YZY0 column coefs
    __shared__ int physA[32], physB[64];        // trace index tables
    __shared__ float partial[4][1024];          // trace partials (16 KB)

    const int tid = threadIdx.x;
    const int b   = blockIdx.x;

    // ---- Fused M = Ry(t2) Rz(t1) Ry(t0) = [[a, -conj b],[b, conj a]] ----
    if (tid < NMAT) {
        int base = tid * 3;
        float t0 = w[base], t1 = w[base + 1], t2 = w[base + 2];
        float c0, s0, c1, s1, c2, s2;
        sincosf(0.5f * t0, &s0, &c0);
        sincosf(0.5f * t1, &s1, &c1);
        sincosf(0.5f * t2, &s2, &c2);
        float2 em = make_float2(c1, -s1);
        float2 ep = make_float2(c1,  s1);
        // alpha = fm0, beta = fm2 (SU(2) verified: fm3 = conj fm0, fm1 = -conj fm2)
        Am[tid] = make_float2( c2*c0*em.x - s2*s0*ep.x,  c2*c0*em.y - s2*s0*ep.y);
        Bm[tid] = make_float2( s2*c0*em.x + c2*s0*ep.x,  s2*c0*em.y + c2*s0*ep.y);
    }
    // ---- Embedding fused into block 0 ----
    if (tid < NQ) {
        float sh, ch;
        sincosf(0.5f * x[b * NQ + tid], &sh, &ch);
        // needs Am/Bm[tid] written by this same thread above (tid < NQ < NMAT)
        float2 al = Am[tid], be = Bm[tid];
        u[tid][0] = make_float2(al.x * ch - be.x * sh, al.y * ch + be.y * sh);
        u[tid][1] = make_float2(be.x * ch + al.x * sh, be.y * ch - al.y * sh);
    }
    // ---- Trace permutation tables ----
    if (tid >= 64 && tid < 96) {
        int j = tid - 64; unsigned ph = 0;
        #pragma unroll
        for (int bit = 0; bit < 5; bit++) if ((j >> bit) & 1) ph ^= dTB.g[bit];
        physA[j] = (int)ph;
    }
    if (tid < 64) {
        int i = tid; unsigned ph = 0;
        #pragma unroll
        for (int bit = 0; bit < 6; bit++) if ((i >> bit) & 1) ph ^= dTB.g[5 + bit];
        physB[i] = (int)ph;
    }
    __syncthreads();

    // ---- Product-state init: 4 consecutive amps per thread ----
    {
        float2 hi = cmul(u[0][(tid >> 8) & 1], u[1][(tid >> 7) & 1]);
        hi = cmul(hi, u[2][(tid >> 6) & 1]);
        hi = cmul(hi, u[3][(tid >> 5) & 1]);
        hi = cmul(hi, u[4][(tid >> 4) & 1]);
        hi = cmul(hi, u[5][(tid >> 3) & 1]);
        hi = cmul(hi, u[6][(tid >> 2) & 1]);
        hi = cmul(hi, u[7][(tid >> 1) & 1]);
        hi = cmul(hi, u[8][tid & 1]);
        #pragma unroll
        for (int k = 0; k < 4; k++) {
            float2 lo = cmul(u[9][(k >> 1) & 1], u[10][k & 1]);
            st[(tid << 2) | k] = cmul(hi, lo);
        }
    }
    __syncthreads();

    // ---- Blocks 1..5: two rounds each, gates in registers/shuffles ----
    do_layer<0>(st, Am, Bm, tid);
    do_layer<1>(st, Am, Bm, tid);
    do_layer<2>(st, Am, Bm, tid);
    do_layer<3>(st, Am, Bm, tid);
    do_layer<4>(st, Am, Bm, tid);

    // ---- Partial trace: Re(rho[j,k]) = sum_i Re(psi_ij psi_ik*) ----
    const int dimA = decode_dimA(dimA_p, B, out_size);
    const int dA   = 1 << dimA;
    const int dB   = NDIM >> dimA;
    const int nOut = dA * dA;
    const bool real_only = ((long long)B * nOut == (long long)out_size);

    if (dimA == 5 && real_only) {
        // 4 i-groups x 128 threads; each thread computes a 2x4 tile over 16 i's
        int g  = tid >> 7;           // 0..3
        int ss = tid & 127;
        int j0 = (ss >> 3) * 2;      // rows: 16 pairs
        int k0 = (ss & 7) * 4;       // cols: 8 quads
        int paj0 = physA[j0], paj1 = physA[j0 + 1];
        int pak[4];
        #pragma unroll
        for (int d = 0; d < 4; d++) pak[d] = physA[k0 + d];
        float acc[2][4];
        #pragma unroll
        for (int a = 0; a < 2; a++)
            #pragma unroll
            for (int c = 0; c < 4; c++) acc[a][c] = 0.f;
        #pragma unroll
        for (int ii = 0; ii < 16; ii++) {
            int pb = physB[g * 16 + ii];
            float2 aj0 = st[pb ^ paj0];
            float2 aj1 = st[pb ^ paj1];
            #pragma unroll
            for (int c = 0; c < 4; c++) {
                float2 ak = st[pb ^ pak[c]];
                acc[0][c] = fmaf(aj0.x, ak.x, fmaf(aj0.y, ak.y, acc[0][c]));
                acc[1][c] = fmaf(aj1.x, ak.x, fmaf(aj1.y, ak.y, acc[1][c]));
            }
        }
        #pragma unroll
        for (int a = 0; a < 2; a++)
            #pragma unroll
            for (int c = 0; c < 4; c++)
                partial[g][(j0 + a) * 32 + (k0 + c)] = acc[a][c];
        __syncthreads();
        #pragma unroll
        for (int m = 0; m < 2; m++) {
            int o = tid * 2 + m;
            ((float*)out_v)[b * 1024 + o] =
                partial[0][o] + partial[1][o] + partial[2][o] + partial[3][o];
        }
    } else {
        // Generic fallback
        for (int o = tid; o < nOut; o += blockDim.x) {
            int j = o / dA;
            int k = o - j * dA;
            float2 acc = make_float2(0.f, 0.f);
            for (int i = 0; i < dB; i++) {
                int lj = i * dA + j, lk = i * dA + k;
                unsigned pj = 0, pk = 0;
                #pragma unroll
                for (int bit = 0; bit < NQ; bit++) {
                    if ((lj >> bit) & 1) pj ^= dTB.g[bit];
                    if ((lk >> bit) & 1) pk ^= dTB.g[bit];
                }
                float2 a = st[pj], c = st[pk];
                acc.x = fmaf(a.x, c.x, fmaf(a.y, c.y, acc.x));
                acc.y = fmaf(a.y, c.x, fmaf(-a.x, c.y, acc.y));
            }
            if (real_only) ((float*)out_v)[b * nOut + o] = acc.x;
            else           ((float2*)out_v)[b * nOut + o] = acc;
        }
    }
}

extern "C" void kernel_launch(void* const* d_in, const int* in_sizes, int n_in,
                              void* d_out, int out_size) {
    // Bind by element count (unique sizes): w=198, dimA=1, x = B*11
    const float* x = nullptr;
    const float* w = nullptr;
    const int* dimA_p = nullptr;
    int x_size = 0;
    for (int i = 0; i < n_in; i++) {
        if (in_sizes[i] == W_SIZE) w = (const float*)d_in[i];
        else if (in_sizes[i] == 1) dimA_p = (const int*)d_in[i];
        else { x = (const float*)d_in[i]; x_size = in_sizes[i]; }
    }
    if (!x) { x = (const float*)d_in[0]; x_size = in_sizes[0]; }
    if (!w) { w = (const float*)d_in[1]; }

    int B = x_size / NQ;   // 16
    qsim_kernel<<<B, 512>>>(x, w, dimA_p, d_out, B, out_size);
}

// round 10
// speedup vs baseline: 1.3401x; 1.0135x over previous
#include <cuda_runtime.h>
#include <cuda_bf16.h>

typedef unsigned long long u64;

#define NQ 11
#define NDIM 2048                 // 1 << NQ
#define NLAYERS 5
#define NBLK (NLAYERS + 1)        // 6 YZY blocks
#define NMAT (NBLK * NQ)          // 66 fused matrices
#define W_SIZE (3 * NMAT)         // 198

// ---------- packed f32x2 helpers (FFMA2 is PTX-only on sm_103a) ----------
__device__ __forceinline__ u64 pk(float lo, float hi) {
    u64 r; asm("mov.b64 %0, {%1, %2};" : "=l"(r) : "f"(lo), "f"(hi)); return r;
}
__device__ __forceinline__ void upk(u64 v, float& lo, float& hi) {
    asm("mov.b64 {%0, %1}, %2;" : "=f"(lo), "=f"(hi) : "l"(v));
}
__device__ __forceinline__ u64 swp(u64 v) {
    float lo, hi; upk(v, lo, hi); return pk(hi, lo);
}
__device__ __forceinline__ u64 fma2(u64 a, u64 b, u64 c) {
    u64 r; asm("fma.rn.f32x2 %0, %1, %2, %3;" : "=l"(r) : "l"(a), "l"(b), "l"(c)); return r;
}
__device__ __forceinline__ u64 mul2(u64 a, u64 b) {
    u64 r; asm("mul.rn.f32x2 %0, %1, %2;" : "=l"(r) : "l"(a), "l"(b)); return r;
}

__device__ __forceinline__ float2 cmul(float2 a, float2 b) {
    return make_float2(a.x * b.x - a.y * b.y, a.x * b.y + a.y * b.x);
}

// ---------- Compile-time GF(2) CNOT-ring tracking ----------
struct Tabs {
    unsigned v[NLAYERS][NQ];   // gate-axis XOR vectors (G columns) per layer/qubit
    unsigned g[NQ];            // final G columns (trace permutation)
};
constexpr Tabs make_tabs() {
    Tabs T{};
    unsigned frow[NQ]{}, gcol[NQ]{};
    for (int i = 0; i < NQ; i++) { frow[i] = 1u << i; gcol[i] = 1u << i; }
    for (int L = 0; L < NLAYERS; L++) {
        for (int q = 0; q < NQ; q++) {
            const int bc = NQ - 1 - q;
            const int bt = NQ - 1 - ((q + 1) % NQ);
            frow[bt] ^= frow[bc];
            gcol[bc] ^= gcol[bt];
        }
        for (int q = 0; q < NQ; q++) T.v[L][q] = gcol[NQ - 1 - q];
    }
    for (int i = 0; i < NQ; i++) T.g[i] = gcol[i];
    return T;
}
constexpr Tabs TB = make_tabs();            // compile-time folded constants
__constant__ Tabs dTB = make_tabs();        // device mirror for runtime accesses

__device__ __forceinline__ int decode_dimA(const int* p, int B, int out_size) {
    int d = -1;
    if (p) {
        int v = p[0];
        if (v >= 1 && v <= NQ) d = v;
        else {
            float f = __int_as_float(v);
            if (f >= 0.5f && f <= 11.5f) d = (int)(f + 0.5f);
        }
    }
    if (d < 1 || d > NQ) {
        for (int t = 1; t <= NQ; t++) {
            long long nc = (long long)B << (2 * t);
            if (nc == (long long)out_size || 2 * nc == (long long)out_size) { d = t; break; }
        }
    }
    if (d < 1 || d > NQ) d = 5;
    return d;
}

// Packed gate splats, indices: 0=axx 1=ayy 2=cayy 3=bxx 4=byy 5=nbxx
// SU(2) gate M = [[al, -conj(be)], [be, conj(al)]] applied to pair (za, zb):
//   al*z       = axx*z  + ayy*swp(z)      axx=(al.x,al.x)  ayy=(-al.y, al.y)
//   conj(al)*z = axx*z  + cayy*swp(z)     cayy=(al.y,-al.y)
//   be*z       = bxx*z  + byy*swp(z)      bxx=(be.x,be.x)  byy=(-be.y, be.y)
//  -conj(be)*z = nbxx*z + byy*swp(z)      nbxx=(-be.x,-be.x)
__device__ __forceinline__ void reg_gate(u64& za, u64& zb, const u64* G) {
    u64 zas = swp(za), zbs = swp(zb);
    u64 na = fma2(G[4], zbs, fma2(G[5], zb, fma2(G[1], zas, mul2(G[0], za))));
    u64 nb = fma2(G[2], zbs, fma2(G[0], zb, fma2(G[4], zas, mul2(G[3], za))));
    za = na; zb = nb;
}

template<int MASK>
__device__ __forceinline__ void lane_gate(u64 z[4], const u64* G, int lane) {
    bool bit = (lane & MASK) != 0;
    u64 cxx = G[0];                     // al.x == conj(al).x
    u64 cyy = bit ? G[2] : G[1];        // conj(al) : al
    u64 dxx = bit ? G[3] : G[5];        // be : -conj(be)
    u64 dyy = G[4];                     // shared
    #pragma unroll
    for (int k = 0; k < 4; k++) {
        float lo, hi; upk(z[k], lo, hi);
        float plo = __shfl_xor_sync(0xffffffffu, lo, MASK);
        float phi = __shfl_xor_sync(0xffffffffu, hi, MASK);
        u64 zp = pk(plo, phi);
        z[k] = fma2(dyy, swp(zp), fma2(dxx, zp, fma2(cyy, swp(z[k]), mul2(cxx, z[k]))));
    }
}

// One YZY block (block L+1) in y-coordinates: p(y) = XOR of v_q for set y_q.
template<int L>
__device__ __forceinline__ void do_layer(u64* st, const u64 (*pg)[6], int tid) {
    constexpr unsigned v0 = TB.v[L][0],  v1 = TB.v[L][1],  v2 = TB.v[L][2];
    constexpr unsigned v3 = TB.v[L][3],  v4 = TB.v[L][4],  v5 = TB.v[L][5];
    constexpr unsigned v6 = TB.v[L][6],  v7 = TB.v[L][7],  v8 = TB.v[L][8];
    constexpr unsigned v9 = TB.v[L][9],  v10 = TB.v[L][10];
    const int lane = tid & 31, wrp = tid >> 5;
    const int mb = (L + 1) * NQ;
    u64 z[4];

    // ---- Round 1: y0,y1 in registers; y2..y6 on lanes; y7..y10 on warps ----
    {
        unsigned base = ((lane & 1) ? v2 : 0u) ^ ((lane & 2) ? v3 : 0u)
                      ^ ((lane & 4) ? v4 : 0u) ^ ((lane & 8) ? v5 : 0u)
                      ^ ((lane & 16) ? v6 : 0u)
                      ^ ((wrp & 1) ? v7 : 0u) ^ ((wrp & 2) ? v8 : 0u)
                      ^ ((wrp & 4) ? v9 : 0u) ^ ((wrp & 8) ? v10 : 0u);
        unsigned a0 = base, a1 = base ^ v0, a2 = base ^ v1, a3 = base ^ v0 ^ v1;
        z[0] = st[a0]; z[1] = st[a1]; z[2] = st[a2]; z[3] = st[a3];
        { const u64* G = pg[mb + 0]; reg_gate(z[0], z[1], G); reg_gate(z[2], z[3], G); }
        { const u64* G = pg[mb + 1]; reg_gate(z[0], z[2], G); reg_gate(z[1], z[3], G); }
        lane_gate<1 >(z, pg[mb + 2], lane);
        lane_gate<2 >(z, pg[mb + 3], lane);
        lane_gate<4 >(z, pg[mb + 4], lane);
        lane_gate<8 >(z, pg[mb + 5], lane);
        lane_gate<16>(z, pg[mb + 6], lane);
        st[a0] = z[0]; st[a1] = z[1]; st[a2] = z[2]; st[a3] = z[3];
        __syncthreads();
    }
    // ---- Round 2: y7,y8 in registers; y9,y10 (+y0..y2) on lanes ----
    {
        unsigned base = ((lane & 1) ? v9 : 0u) ^ ((lane & 2) ? v10 : 0u)
                      ^ ((lane & 4) ? v0 : 0u) ^ ((lane & 8) ? v1 : 0u)
                      ^ ((lane & 16) ? v2 : 0u)
                      ^ ((wrp & 1) ? v3 : 0u) ^ ((wrp & 2) ? v4 : 0u)
                      ^ ((wrp & 4) ? v5 : 0u) ^ ((wrp & 8) ? v6 : 0u);
        unsigned a0 = base, a1 = base ^ v7, a2 = base ^ v8, a3 = base ^ v7 ^ v8;
        z[0] = st[a0]; z[1] = st[a1]; z[2] = st[a2]; z[3] = st[a3];
        { const u64* G = pg[mb + 7]; reg_gate(z[0], z[1], G); reg_gate(z[2], z[3], G); }
        { const u64* G = pg[mb + 8]; reg_gate(z[0], z[2], G); reg_gate(z[1], z[3], G); }
        lane_gate<1>(z, pg[mb + 9],  lane);
        lane_gate<2>(z, pg[mb + 10], lane);
        st[a0] = z[0]; st[a1] = z[1]; st[a2] = z[2]; st[a3] = z[3];
        __syncthreads();
    }
}

__global__ __launch_bounds__(512)
void qsim_kernel(const float* __restrict__ x,
                 const float* __restrict__ w,
                 const int* __restrict__ dimA_p,
                 void* __restrict__ out_v,
                 int B, int out_size)
{
    __shared__ u64 st[NDIM];                    // packed statevector (16 KB)
    __shared__ u64 pg[NMAT][6];                 // packed gate splats (3.1 KB)
    __shared__ float2 u[NQ][2];                 // embed*YZY0 column coefs
    __shared__ int physA[32], physB[64];        // trace index tables
    __shared__ float partial[4][1024];          // trace partials (16 KB)

    const int tid = threadIdx.x;
    const int b   = blockIdx.x;

    // ---- Fused M = Ry(t2) Rz(t1) Ry(t0); store packed splats ----
    float2 al0, be0;                            // kept for embedding (tid < NQ)
    if (tid < NMAT) {
        int base = tid * 3;
        float t0 = w[base], t1 = w[base + 1], t2 = w[base + 2];
        float c0, s0, c1, s1, c2, s2;
        sincosf(0.5f * t0, &s0, &c0);
        sincosf(0.5f * t1, &s1, &c1);
        sincosf(0.5f * t2, &s2, &c2);
        float2 em = make_float2(c1, -s1);
        float2 ep = make_float2(c1,  s1);
        float2 al = make_float2( c2*c0*em.x - s2*s0*ep.x,  c2*c0*em.y - s2*s0*ep.y);
        float2 be = make_float2( s2*c0*em.x + c2*s0*ep.x,  s2*c0*em.y + c2*s0*ep.y);
        pg[tid][0] = pk(al.x, al.x);
        pg[tid][1] = pk(-al.y, al.y);
        pg[tid][2] = pk(al.y, -al.y);
        pg[tid][3] = pk(be.x, be.x);
        pg[tid][4] = pk(-be.y, be.y);
        pg[tid][5] = pk(-be.x, -be.x);
        al0 = al; be0 = be;
    }
    // ---- Embedding fused into block 0 ----
    if (tid < NQ) {
        float sh, ch;
        sincosf(0.5f * x[b * NQ + tid], &sh, &ch);
        u[tid][0] = make_float2(al0.x * ch - be0.x * sh, al0.y * ch + be0.y * sh);
        u[tid][1] = make_float2(be0.x * ch + al0.x * sh, be0.y * ch - al0.y * sh);
    }
    // ---- Trace permutation tables ----
    if (tid >= 64 && tid < 96) {
        int j = tid - 64; unsigned ph = 0;
        #pragma unroll
        for (int bit = 0; bit < 5; bit++) if ((j >> bit) & 1) ph ^= dTB.g[bit];
        physA[j] = (int)ph;
    }
    if (tid < 64) {
        int i = tid; unsigned ph = 0;
        #pragma unroll
        for (int bit = 0; bit < 6; bit++) if ((i >> bit) & 1) ph ^= dTB.g[5 + bit];
        physB[i] = (int)ph;
    }
    __syncthreads();

    // ---- Product-state init: 4 consecutive amps per thread ----
    {
        float2 hi = cmul(u[0][(tid >> 8) & 1], u[1][(tid >> 7) & 1]);
        hi = cmul(hi, u[2][(tid >> 6) & 1]);
        hi = cmul(hi, u[3][(tid >> 5) & 1]);
        hi = cmul(hi, u[4][(tid >> 4) & 1]);
        hi = cmul(hi, u[5][(tid >> 3) & 1]);
        hi = cmul(hi, u[6][(tid >> 2) & 1]);
        hi = cmul(hi, u[7][(tid >> 1) & 1]);
        hi = cmul(hi, u[8][tid & 1]);
        #pragma unroll
        for (int k = 0; k < 4; k++) {
            float2 lo = cmul(u[9][(k >> 1) & 1], u[10][k & 1]);
            float2 r = cmul(hi, lo);
            st[(tid << 2) | k] = pk(r.x, r.y);
        }
    }
    __syncthreads();

    // ---- Blocks 1..5 ----
    do_layer<0>(st, pg, tid);
    do_layer<1>(st, pg, tid);
    do_layer<2>(st, pg, tid);
    do_layer<3>(st, pg, tid);
    do_layer<4>(st, pg, tid);

    // ---- Partial trace: Re(rho[j,k]) = sum_i Re(psi_ij psi_ik*) ----
    const int dimA = decode_dimA(dimA_p, B, out_size);
    const int dA   = 1 << dimA;
    const int dB   = NDIM >> dimA;
    const int nOut = dA * dA;
    const bool real_only = ((long long)B * nOut == (long long)out_size);

    if (dimA == 5 && real_only) {
        // 4 i-groups x 128 threads; 2x4 register tiles over 16 i's; packed dot
        int g  = tid >> 7;
        int ss = tid & 127;
        int j0 = (ss >> 3) * 2;
        int k0 = (ss & 7) * 4;
        int paj0 = physA[j0], paj1 = physA[j0 + 1];
        int pak[4];
        #pragma unroll
        for (int d = 0; d < 4; d++) pak[d] = physA[k0 + d];
        u64 acc2[2][4];
        #pragma unroll
        for (int a = 0; a < 2; a++)
            #pragma unroll
            for (int c = 0; c < 4; c++) acc2[a][c] = 0ull;
        #pragma unroll
        for (int ii = 0; ii < 16; ii++) {
            int pb = physB[g * 16 + ii];
            u64 aj0 = st[pb ^ paj0];
            u64 aj1 = st[pb ^ paj1];
            #pragma unroll
            for (int c = 0; c < 4; c++) {
                u64 ak = st[pb ^ pak[c]];
                acc2[0][c] = fma2(aj0, ak, acc2[0][c]);   // (x*x, y*y) lanes
                acc2[1][c] = fma2(aj1, ak, acc2[1][c]);
            }
        }
        #pragma unroll
        for (int a = 0; a < 2; a++)
            #pragma unroll
            for (int c = 0; c < 4; c++) {
                float sx, sy; upk(acc2[a][c], sx, sy);
                partial[g][(j0 + a) * 32 + (k0 + c)] = sx + sy;
            }
        __syncthreads();
        #pragma unroll
        for (int m = 0; m < 2; m++) {
            int o = tid * 2 + m;
            ((float*)out_v)[b * 1024 + o] =
                partial[0][o] + partial[1][o] + partial[2][o] + partial[3][o];
        }
    } else {
        // Generic fallback (scalar)
        for (int o = tid; o < nOut; o += blockDim.x) {
            int j = o / dA;
            int k = o - j * dA;
            float2 acc = make_float2(0.f, 0.f);
            for (int i = 0; i < dB; i++) {
                int lj = i * dA + j, lk = i * dA + k;
                unsigned pj = 0, pkk = 0;
                #pragma unroll
                for (int bit = 0; bit < NQ; bit++) {
                    if ((lj >> bit) & 1) pj ^= dTB.g[bit];
                    if ((lk >> bit) & 1) pkk ^= dTB.g[bit];
                }
                float ax, ay, cx, cy;
                upk(st[pj], ax, ay);
                upk(st[pkk], cx, cy);
                acc.x = fmaf(ax, cx, fmaf(ay, cy, acc.x));
                acc.y = fmaf(ay, cx, fmaf(-ax, cy, acc.y));
            }
            if (real_only) ((float*)out_v)[b * nOut + o] = acc.x;
            else           ((float2*)out_v)[b * nOut + o] = acc;
        }
    }
}

extern "C" void kernel_launch(void* const* d_in, const int* in_sizes, int n_in,
                              void* d_out, int out_size) {
    // Bind by element count (unique sizes): w=198, dimA=1, x = B*11
    const float* x = nullptr;
    const float* w = nullptr;
    const int* dimA_p = nullptr;
    int x_size = 0;
    for (int i = 0; i < n_in; i++) {
        if (in_sizes[i] == W_SIZE) w = (const float*)d_in[i];
        else if (in_sizes[i] == 1) dimA_p = (const int*)d_in[i];
        else { x = (const float*)d_in[i]; x_size = in_sizes[i]; }
    }
    if (!x) { x = (const float*)d_in[0]; x_size = in_sizes[0]; }
    if (!w) { w = (const float*)d_in[1]; }

    int B = x_size / NQ;   // 16
    qsim_kernel<<<B, 512>>>(x, w, dimA_p, d_out, B, out_size);
}